// round 1
// baseline (speedup 1.0000x reference)
#include <cuda_runtime.h>
#include <float.h>

// SparseSoftmax: masked softmax over last axis.
// features: (32, 2048, 2048) fp32, OD: same shape int32 (mask = OD != 0).
// out[b,i,j] = mask ? exp(f - rowmax_masked) / sum_masked : 0
// Fully-masked rows -> all zeros.
//
// Strategy: one CTA per row (65536 rows). 256 threads x 8 elements each,
// register-resident row. Single read of f + OD, single write of out.

#define ROW_LEN 2048
#define THREADS 256
#define ELEMS_PER_THREAD 8   // 2 x float4 per thread

__global__ __launch_bounds__(THREADS, 8)
void sparse_softmax_kernel(const float* __restrict__ f,
                           const int* __restrict__ od,
                           float* __restrict__ out)
{
    const int row = blockIdx.x;
    const size_t base = (size_t)row * ROW_LEN;
    const float4* __restrict__ f4 = reinterpret_cast<const float4*>(f + base);
    const int4*   __restrict__ o4 = reinterpret_cast<const int4*>(od + base);
    float4* __restrict__ out4 = reinterpret_cast<float4*>(out + base);

    const int t = threadIdx.x;

    // Load 8 floats + 8 mask ints into registers (coalesced 16B accesses).
    float4 v0 = f4[t];
    float4 v1 = f4[t + THREADS];
    int4   m0 = o4[t];
    int4   m1 = o4[t + THREADS];

    float vals[ELEMS_PER_THREAD] = {v0.x, v0.y, v0.z, v0.w, v1.x, v1.y, v1.z, v1.w};
    int   msk [ELEMS_PER_THREAD] = {m0.x, m0.y, m0.z, m0.w, m1.x, m1.y, m1.z, m1.w};

    // --- local max over unmasked lanes ---
    float mx = -FLT_MAX;
    #pragma unroll
    for (int i = 0; i < ELEMS_PER_THREAD; i++) {
        if (msk[i] != 0) mx = fmaxf(mx, vals[i]);
    }

    // --- block reduce max ---
    __shared__ float smax[8];
    __shared__ float sbuf[8];
    __shared__ float s_rowmax;
    __shared__ float s_inv;

    #pragma unroll
    for (int o = 16; o > 0; o >>= 1)
        mx = fmaxf(mx, __shfl_xor_sync(0xffffffffu, mx, o));
    const int warp = t >> 5;
    const int lane = t & 31;
    if (lane == 0) smax[warp] = mx;
    __syncthreads();
    if (t == 0) {
        float m = smax[0];
        #pragma unroll
        for (int w = 1; w < 8; w++) m = fmaxf(m, smax[w]);
        s_rowmax = m;
    }
    __syncthreads();
    const float rowmax = s_rowmax;

    // --- exp + local sum (exp only on unmasked lanes; vals-rowmax <= 0) ---
    float p[ELEMS_PER_THREAD];
    float sum = 0.0f;
    #pragma unroll
    for (int i = 0; i < ELEMS_PER_THREAD; i++) {
        float e = (msk[i] != 0) ? __expf(vals[i] - rowmax) : 0.0f;
        p[i] = e;
        sum += e;
    }

    // --- block reduce sum ---
    #pragma unroll
    for (int o = 16; o > 0; o >>= 1)
        sum += __shfl_xor_sync(0xffffffffu, sum, o);
    if (lane == 0) sbuf[warp] = sum;
    __syncthreads();
    if (t == 0) {
        float s = 0.0f;
        #pragma unroll
        for (int w = 0; w < 8; w++) s += sbuf[w];
        s_inv = (s > 0.0f) ? (1.0f / s) : 0.0f;
    }
    __syncthreads();
    const float inv = s_inv;

    // --- normalize + write (fully-masked rows: inv==0 -> zeros) ---
    float4 r0 = make_float4(p[0] * inv, p[1] * inv, p[2] * inv, p[3] * inv);
    float4 r1 = make_float4(p[4] * inv, p[5] * inv, p[6] * inv, p[7] * inv);
    out4[t]            = r0;
    out4[t + THREADS]  = r1;
}

extern "C" void kernel_launch(void* const* d_in, const int* in_sizes, int n_in,
                              void* d_out, int out_size)
{
    const float* features = (const float*)d_in[0];
    const int*   OD       = (const int*)d_in[1];
    float*       out      = (float*)d_out;

    const int rows = in_sizes[0] / ROW_LEN;   // 32*2048 = 65536
    sparse_softmax_kernel<<<rows, THREADS>>>(features, OD, out);
}